// round 7
// baseline (speedup 1.0000x reference)
#include <cuda_runtime.h>
#include <math.h>

#define KK 10
#define NN 96
#define TT 40
#define HD 48
#define NROW 960          // K*N
#define NBINS 36
#define NBLK 120          // 12 leader blocks + 108 follower (proj) blocks
#define RPB 8             // rows per block (120*8 = 960)
#define NTHR 256
#define PROJ_STRIDE (NN*1728)   // 165888 floats per step

// -------- device scratch (static allocation only) ---------------------------
__device__ __align__(16) float g_out1[16*80*80];
__device__ __align__(16) float g_fmapT[80*80*32];        // [pix][c]
__device__ __align__(16) float g_xpre[TT*NROW*48];       // [t][row][c]
__device__ int   g_nbcnt[TT*NROW];
__device__ int   g_nbbin[TT*NROW*NBINS];                  // (bin<<16)|winner
__device__ float g_nbinv[TT*NROW*NBINS];
__device__ __align__(16) float g_hhist[(TT+1)*NN*HD];     // hidden history (96 rows/t)
__device__ __align__(16) float g_proj[(size_t)TT*PROJ_STRIDE]; // per-t proj buffers
__device__ __align__(16) float g_wihT[96*144];
__device__ __align__(16) float g_whhT[48*144];
__device__ __align__(16) float g_scfT[1728*48];           // [bin*48+h][o]
__device__ unsigned g_hflag[TT + 1];                      // hidden[t] ready (12)
__device__ unsigned g_pflag[TT];                          // proj[t] ready (108)

// -------- release/acquire primitives ----------------------------------------
__device__ __forceinline__ void bar_arrive(unsigned* a) {
    asm volatile("red.release.gpu.global.add.u32 [%0], 1;" :: "l"(a) : "memory");
}
__device__ __forceinline__ void bar_wait(unsigned* a, unsigned tgt) {
    unsigned v;
    while (true) {
        asm volatile("ld.acquire.gpu.global.u32 %0, [%1];" : "=r"(v) : "l"(a) : "memory");
        if (v >= tgt) break;
        __nanosleep(32);
    }
}

// ---------------------------------------------------------------------------
// conv1: img (1,4,160,160) -> out1 (16,80,80), stride 2, pad 2, k=5, relu
__global__ void k_conv1(const float* __restrict__ img,
                        const float* __restrict__ w1,
                        const float* __restrict__ b1) {
    int idx = blockIdx.x * blockDim.x + threadIdx.x;
    if (idx >= 16*80*80) return;
    int ox = idx % 80;
    int oy = (idx / 80) % 80;
    int oc = idx / 6400;
    float acc = b1[oc];
    int iy0 = oy*2 - 2, ix0 = ox*2 - 2;
    for (int ic = 0; ic < 4; ic++) {
        #pragma unroll
        for (int ky = 0; ky < 5; ky++) {
            int iy = iy0 + ky;
            if ((unsigned)iy >= 160u) continue;
            #pragma unroll
            for (int kx = 0; kx < 5; kx++) {
                int ix = ix0 + kx;
                if ((unsigned)ix >= 160u) continue;
                acc = fmaf(__ldg(&img[(ic*160 + iy)*160 + ix]),
                           __ldg(&w1[((oc*4 + ic)*5 + ky)*5 + kx]), acc);
            }
        }
    }
    g_out1[idx] = fmaxf(acc, 0.f);
}

// conv2: out1 (16,80,80) -> fmapT (80*80,32), stride 1, pad 2, k=5, relu
__global__ void k_conv2(const float* __restrict__ w2,
                        const float* __restrict__ b2) {
    __shared__ float in_s[16*20*20];
    __shared__ float w_s[400];
    int oc  = blockIdx.z;
    int ty0 = blockIdx.y * 16;
    int tx0 = blockIdx.x * 16;
    int tid = threadIdx.x;

    for (int i = tid; i < 400; i += 256) w_s[i] = w2[oc*400 + i];
    for (int i = tid; i < 16*400; i += 256) {
        int ic  = i / 400;
        int rem = i % 400;
        int yy  = rem / 20, xx = rem % 20;
        int gy  = ty0 - 2 + yy, gx = tx0 - 2 + xx;
        in_s[i] = (gy >= 0 && gy < 80 && gx >= 0 && gx < 80)
                  ? g_out1[(ic*80 + gy)*80 + gx] : 0.f;
    }
    __syncthreads();

    int lx = tid % 16, ly = tid / 16;
    float acc = b2[oc];
    for (int ic = 0; ic < 16; ic++) {
        #pragma unroll
        for (int ky = 0; ky < 5; ky++) {
            #pragma unroll
            for (int kx = 0; kx < 5; kx++) {
                acc = fmaf(in_s[ic*400 + (ly + ky)*20 + (lx + kx)],
                           w_s[(ic*5 + ky)*5 + kx], acc);
            }
        }
    }
    g_fmapT[((ty0 + ly)*80 + tx0 + lx)*32 + oc] = fmaxf(acc, 0.f);
}

// ---------------------------------------------------------------------------
// fused pre-kernel: weight transposes + hhist[0] + flags | xpre | bins
#define SEG0 (1728*48)
#define SEG1 (SEG0 + 96*144)
#define SEG2 (SEG1 + 48*144)
#define SEG3 (SEG2 + NN*HD)
#define PREP_N (SEG3 + (TT + 1) + TT)
#define PREP_B ((PREP_N + 255)/256)
#define XPRE_B ((TT*NROW + 255)/256)
#define BINS_B ((TT*NROW + 255)/256)
__global__ void k_pre(const float* __restrict__ hx,
                      const float* __restrict__ wih,
                      const float* __restrict__ whh,
                      const float* __restrict__ scfw,
                      const float* __restrict__ ypath,
                      const float* __restrict__ curloc,
                      const float* __restrict__ fvw,
                      const float* __restrict__ fvb) {
    int b = blockIdx.x;
    if (b < PREP_B) {
        int i = b*256 + threadIdx.x;
        if (i < SEG0) {
            int in = i / 48, o = i % 48;
            g_scfT[i] = scfw[o*1728 + in];
        } else if (i < SEG1) {
            int j = i - SEG0;
            int c = j / 144, g = j % 144;
            g_wihT[j] = wih[g*96 + c];
        } else if (i < SEG2) {
            int j = i - SEG1;
            int c = j / 144, g = j % 144;
            g_whhT[j] = whh[g*48 + c];
        } else if (i < SEG3) {
            g_hhist[i - SEG2] = hx[i - SEG2];
        } else if (i < SEG3 + TT + 1) {
            g_hflag[i - SEG3] = 0;
        } else if (i < PREP_N) {
            g_pflag[i - SEG3 - (TT + 1)] = 0;
        }
        return;
    }
    if (b < PREP_B + XPRE_B) {
        int idx = (b - PREP_B)*256 + threadIdx.x;
        if (idx >= TT*NROW) return;
        int t  = idx / NROW;
        int kn = idx % NROW;
        int k  = kn / NN, n = kn % NN;
        const float* yp = ypath + ((size_t)(k*TT + t)*NN + n)*2;
        float lx = yp[0], ly = yp[1];
        int ui = 40 - (int)ly;     // trunc matches astype(int32)
        int vi = 40 - (int)lx;
        ui = min(max(ui, 0), 79);
        vi = min(max(vi, 0), 79);
        const float4* fp = (const float4*)(g_fmapT + (ui*80 + vi)*32);
        float4* xp = (float4*)(g_xpre + (size_t)idx*48);
        #pragma unroll
        for (int q = 0; q < 8; q++) xp[q] = fp[q];
        float px, py;
        if (t == 0) { px = curloc[n*2]; py = curloc[n*2 + 1]; }
        else {
            const float* pp = ypath + ((size_t)(k*TT + t - 1)*NN + n)*2;
            px = pp[0]; py = pp[1];
        }
        float vx = (lx - px) * 10.f;
        float vy = (ly - py) * 10.f;
        float* xo = g_xpre + (size_t)idx*48 + 32;
        #pragma unroll
        for (int f = 0; f < 16; f++)
            xo[f] = fmaxf(fmaf(vx, fvw[f*2], fmaf(vy, fvw[f*2 + 1], fvb[f])), 0.f);
        return;
    }
    {   // bins
        int idx = (b - PREP_B - XPRE_B)*256 + threadIdx.x;
        if (idx >= TT*NROW) return;
        int t  = idx / NROW;
        int kn = idx % NROW;
        int k  = kn / NN, i = kn % NN;
        const float* locb = ypath + (size_t)(k*TT + t)*NN*2;
        float xi = locb[i*2], yi = locb[i*2 + 1];

        const float R0f = 0.5f, R1f = 4.0f;
        const float RSTEPf = (float)((4.0 - 0.5)/6.0);
        const float TSTEPf = (float)(2.0*3.14159265358979323846/6.0);
        const float TWOPIf = (float)(2.0*3.14159265358979323846);

        int winner[NBINS];
        int cnt[NBINS];
        #pragma unroll
        for (int bb = 0; bb < NBINS; bb++) { winner[bb] = -1; cnt[bb] = 0; }

        for (int j = 0; j < NN; j++) {
            if (j == i) continue;
            float cx = locb[j*2]     - xi;
            float cy = locb[j*2 + 1] - yi;
            float dist = __fsqrt_rn(fmaf(cx, cx, cy*cy));
            if (dist < R0f || dist > R1f) continue;
            float dsafe = fmaxf(dist, 1e-10f);
            float cost  = fminf(fmaxf(__fdiv_rn(cx, dsafe), -1.f), 1.f);
            float ac    = acosf(cost);
            float theta = (cy < 0.f) ? (TWOPIf - ac) : ac;
            int ub = (int)__fdiv_rn(dist - R0f, RSTEPf);
            ub = min(max(ub, 0), 5);
            int vb = (int)__fdiv_rn(theta, TSTEPf);
            vb = min(max(vb, 0), 5);
            int bb = ub*6 + vb;
            winner[bb] = j;
            cnt[bb]++;
        }
        int nb = 0;
        int base = idx * NBINS;
        for (int bb = 0; bb < NBINS; bb++) {
            if (winner[bb] >= 0) {
                g_nbbin[base + nb] = (bb << 16) | winner[bb];
                g_nbinv[base + nb] = __fdiv_rn(1.f, (float)cnt[bb]);
                nb++;
            }
        }
        g_nbcnt[idx] = nb;
    }
}

// ---------------------------------------------------------------------------
// persistent kernel: 40 GRU steps + epilogue
__global__ void __launch_bounds__(NTHR, 1) k_steps(
        const float* __restrict__ scfb,
        const float* __restrict__ bih,
        const float* __restrict__ bhh,
        const float* __restrict__ wsc,
        const float* __restrict__ dyw,
        const float* __restrict__ dyb,
        const float* __restrict__ bsc,
        float* __restrict__ out) {
    // overlay: leaders use [hsh 4608 | part 1536]; followers use [sW 2304 | sHid 1536]
    __shared__ __align__(16) float s_big[4608 + 1536];
    __shared__ __align__(16) float xs[96][RPB];    // [c][r]
    __shared__ __align__(16) float hown[48][RPB];  // [h][r]
    __shared__ __align__(16) float gis[144][RPB];
    __shared__ __align__(16) float ghs[144][RPB];
    __shared__ __align__(16) float hns[RPB][48];
    __shared__ int   s_pk[RPB][NBINS];
    __shared__ float s_inv[RPB][NBINS];
    __shared__ int   s_nb[RPB];
    __shared__ float s_score[RPB];

    const int tid  = threadIdx.x;
    const int blk  = blockIdx.x;
    const int row0 = blk * RPB;
    const bool lead = (blk < 12);          // rows 0-95: recurrent pool chain
    const int binA  = (blk - 12) / 3;
    const int partA = (blk - 12) % 3;

    float* HSH  = s_big;            // leader: full hidden[t] (96*48)
    float* PART = s_big + 4608;     // leader: pooling partials (384 float4)
    float* SW   = s_big;            // follower: bin weight (48*48)
    float* SHID = s_big + 2304;     // follower: 32-row hidden slice

    if (tid < RPB) s_score[tid] = 0.f;
    if (!lead) {   // bin weight resident all 40 steps
        const float4* wsrc = (const float4*)(g_scfT + binA*2304);
        for (int i = tid; i < 576; i += NTHR)
            ((float4*)SW)[i] = wsrc[i];
    }
    // local hidden init: row (row0+r) uses hx row (row0+r)%96
    for (int i = tid; i < 48*RPB; i += NTHR) {
        int h = i >> 3, r = i & 7;
        hown[h][r] = g_hhist[((row0 + r) % NN)*HD + h];
    }
    __syncthreads();

    // ---- follower prologue: produce proj[0] (hidden[0] from prior launch)
    if (!lead) {
        const float4* hsrc = (const float4*)(g_hhist) + partA*384;
        for (int i = tid; i < 384; i += NTHR)
            ((float4*)SHID)[i] = hsrc[i];
        __syncthreads();
        for (int task = tid; task < 384; task += NTHR) {
            int j = task / 12, og = task % 12;
            const float* hp = SHID + j*48;
            float4 acc = make_float4(0.f, 0.f, 0.f, 0.f);
            #pragma unroll
            for (int h = 0; h < 48; h++) {
                float4 w4 = *(const float4*)(SW + h*48 + og*4);
                float hv = hp[h];
                acc.x = fmaf(w4.x, hv, acc.x);
                acc.y = fmaf(w4.y, hv, acc.y);
                acc.z = fmaf(w4.z, hv, acc.z);
                acc.w = fmaf(w4.w, hv, acc.w);
            }
            __stcg((float4*)(g_proj + (partA*32 + j)*1728 + binA*48 + og*4), acc);
        }
        __threadfence();
        __syncthreads();
        if (tid == 0) bar_arrive(&g_pflag[0]);
    }

    for (int t = 0; t < TT; t++) {
        // ---- stage lhalf + pooling metadata (no cross-block dep)
        for (int i = tid; i < 48*RPB; i += NTHR) {
            int c = i >> 3, r = i & 7;
            xs[c][r] = g_xpre[(size_t)(t*NROW + row0 + r)*48 + c];
        }
        if (tid < RPB) s_nb[tid] = g_nbcnt[t*NROW + row0 + tid];
        for (int i = tid; i < RPB*NBINS; i += NTHR) {
            int r = i / NBINS, e = i % NBINS;
            s_pk[r][e]  = g_nbbin[(t*NROW + row0 + r)*NBINS + e];
            s_inv[r][e] = g_nbinv[(t*NROW + row0 + r)*NBINS + e];
        }
        __syncthreads();

        // ---- gh (local recurrent rows)
        for (int task = tid; task < 288; task += NTHR) {
            int half = (task >= 144) ? 1 : 0;
            int g = task - half*144;
            float b = bhh[g];
            float4 acc = make_float4(b, b, b, b);
            #pragma unroll 4
            for (int c = 0; c < 48; c++) {
                float w = __ldg(&g_whhT[c*144 + g]);
                float4 hv = ((const float4*)(&hown[c][0]))[half];
                acc.x = fmaf(w, hv.x, acc.x);
                acc.y = fmaf(w, hv.y, acc.y);
                acc.z = fmaf(w, hv.z, acc.z);
                acc.w = fmaf(w, hv.w, acc.w);
            }
            ((float4*)(&ghs[g][0]))[half] = acc;
        }
        // ---- gi_L (lhalf contribution)
        for (int task = tid; task < 288; task += NTHR) {
            int half = (task >= 144) ? 1 : 0;
            int g = task - half*144;
            float b = bih[g];
            float4 acc = make_float4(b, b, b, b);
            #pragma unroll 4
            for (int c = 0; c < 48; c++) {
                float w = __ldg(&g_wihT[c*144 + g]);
                float4 xv = ((const float4*)(&xs[c][0]))[half];
                acc.x = fmaf(w, xv.x, acc.x);
                acc.y = fmaf(w, xv.y, acc.y);
                acc.z = fmaf(w, xv.z, acc.z);
                acc.w = fmaf(w, xv.w, acc.w);
            }
            ((float4*)(&gis[g][0]))[half] = acc;
        }

        if (lead) {
            // =========== LEADER: direct pooling, no follower dependency =====
            if (t > 0) bar_wait(&g_hflag[t], 12);
            const float4* hsrc = (const float4*)(g_hhist + (size_t)t*NN*HD);
            for (int i = tid; i < 1152; i += NTHR)
                ((float4*)HSH)[i] = __ldcg(hsrc + i);
            __syncthreads();
            // pooling: task = ((r*4+hq)*12+og); W streamed from L2/L1
            for (int task = tid; task < 384; task += NTHR) {
                int r = task / 48, rem = task % 48;
                int hq = rem / 12, og = rem % 12;
                int h0 = hq*12;
                int nb = s_nb[r];
                float4 acc = make_float4(0.f, 0.f, 0.f, 0.f);
                for (int e = 0; e < nb; e++) {
                    int pk = s_pk[r][e];
                    float inv = s_inv[r][e];
                    const float* hp = HSH + (pk & 0xffff)*48;
                    const float* wp = g_scfT + (pk >> 16)*2304 + og*4;
                    float4 part = make_float4(0.f, 0.f, 0.f, 0.f);
                    #pragma unroll
                    for (int h = h0; h < h0 + 12; h++) {
                        float4 w4 = __ldg((const float4*)(wp + h*48));
                        float hv = hp[h];
                        part.x = fmaf(w4.x, hv, part.x);
                        part.y = fmaf(w4.y, hv, part.y);
                        part.z = fmaf(w4.z, hv, part.z);
                        part.w = fmaf(w4.w, hv, part.w);
                    }
                    acc.x = fmaf(inv, part.x, acc.x);
                    acc.y = fmaf(inv, part.y, acc.y);
                    acc.z = fmaf(inv, part.z, acc.z);
                    acc.w = fmaf(inv, part.w, acc.w);
                }
                ((float4*)PART)[task] = acc;
            }
            __syncthreads();
            if (tid < 96) {
                int r = tid / 12, og = tid % 12;
                float4 a0 = ((float4*)PART)[(r*4 + 0)*12 + og];
                float4 a1 = ((float4*)PART)[(r*4 + 1)*12 + og];
                float4 a2 = ((float4*)PART)[(r*4 + 2)*12 + og];
                float4 a3 = ((float4*)PART)[(r*4 + 3)*12 + og];
                float4 bb = *(const float4*)(scfb + og*4);
                xs[48 + og*4 + 0][r] = fmaxf(a0.x + a1.x + a2.x + a3.x + bb.x, 0.f);
                xs[48 + og*4 + 1][r] = fmaxf(a0.y + a1.y + a2.y + a3.y + bb.y, 0.f);
                xs[48 + og*4 + 2][r] = fmaxf(a0.z + a1.z + a2.z + a3.z + bb.z, 0.f);
                xs[48 + og*4 + 3][r] = fmaxf(a0.w + a1.w + a2.w + a3.w + bb.w, 0.f);
            }
        } else {
            // =========== FOLLOWER: produce proj[t+1] ahead, then consume t ===
            if (t + 1 < TT) {
                bar_wait(&g_hflag[t + 1], 12);
                const float4* hsrc =
                    (const float4*)(g_hhist + (size_t)(t + 1)*NN*HD) + partA*384;
                for (int i = tid; i < 384; i += NTHR)
                    ((float4*)SHID)[i] = __ldcg(hsrc + i);
                __syncthreads();
                float* projW = g_proj + (size_t)(t + 1)*PROJ_STRIDE;
                for (int task = tid; task < 384; task += NTHR) {
                    int j = task / 12, og = task % 12;
                    const float* hp = SHID + j*48;
                    float4 acc = make_float4(0.f, 0.f, 0.f, 0.f);
                    #pragma unroll
                    for (int h = 0; h < 48; h++) {
                        float4 w4 = *(const float4*)(SW + h*48 + og*4);
                        float hv = hp[h];
                        acc.x = fmaf(w4.x, hv, acc.x);
                        acc.y = fmaf(w4.y, hv, acc.y);
                        acc.z = fmaf(w4.z, hv, acc.z);
                        acc.w = fmaf(w4.w, hv, acc.w);
                    }
                    __stcg((float4*)(projW + (partA*32 + j)*1728 + binA*48 + og*4), acc);
                }
                __threadfence();
                __syncthreads();
                if (tid == 0) bar_arrive(&g_pflag[t + 1]);
            }
            // consume proj[t] (produced one iteration ago -> fast-path detect)
            bar_wait(&g_pflag[t], 108);
            const float* projR = g_proj + (size_t)t*PROJ_STRIDE;
            if (tid < 96) {
                int r = tid / 12, og = tid % 12;
                int nb = s_nb[r];
                float4 acc = *(const float4*)(scfb + og*4);
                for (int base = 0; base < nb; base += 8) {
                    float4 pv[8];
                    float  iv[8];
                    #pragma unroll
                    for (int e = 0; e < 8; e++) {
                        int idx = base + e;
                        if (idx < nb) {
                            int pk = s_pk[r][idx];
                            pv[e] = __ldcg((const float4*)(projR +
                                        (pk & 0xffff)*1728 + (pk >> 16)*48) + og);
                            iv[e] = s_inv[r][idx];
                        }
                    }
                    #pragma unroll
                    for (int e = 0; e < 8; e++) {
                        if (base + e < nb) {
                            acc.x = fmaf(iv[e], pv[e].x, acc.x);
                            acc.y = fmaf(iv[e], pv[e].y, acc.y);
                            acc.z = fmaf(iv[e], pv[e].z, acc.z);
                            acc.w = fmaf(iv[e], pv[e].w, acc.w);
                        }
                    }
                }
                xs[48 + og*4 + 0][r] = fmaxf(acc.x, 0.f);
                xs[48 + og*4 + 1][r] = fmaxf(acc.y, 0.f);
                xs[48 + og*4 + 2][r] = fmaxf(acc.z, 0.f);
                xs[48 + og*4 + 3][r] = fmaxf(acc.w, 0.f);
            }
        }
        __syncthreads();

        // ---- gi_R (rhalf contribution; same thread->task mapping as gi_L)
        for (int task = tid; task < 288; task += NTHR) {
            int half = (task >= 144) ? 1 : 0;
            int g = task - half*144;
            float4 acc = ((const float4*)(&gis[g][0]))[half];
            #pragma unroll 4
            for (int c = 48; c < 96; c++) {
                float w = __ldg(&g_wihT[c*144 + g]);
                float4 xv = ((const float4*)(&xs[c][0]))[half];
                acc.x = fmaf(w, xv.x, acc.x);
                acc.y = fmaf(w, xv.y, acc.y);
                acc.z = fmaf(w, xv.z, acc.z);
                acc.w = fmaf(w, xv.w, acc.w);
            }
            ((float4*)(&gis[g][0]))[half] = acc;
        }
        __syncthreads();

        // ---- GRU elementwise; leaders publish h(t+1) rows
        float* hpub = g_hhist + (size_t)(t + 1)*NN*HD;
        for (int task = tid; task < RPB*48; task += NTHR) {
            int r = task / 48, o = task % 48;
            float gir = gis[o][r],      ghr = ghs[o][r];
            float giz = gis[48 + o][r], ghz = ghs[48 + o][r];
            float gin = gis[96 + o][r], ghn = ghs[96 + o][r];
            float rg = 1.f / (1.f + expf(-(gir + ghr)));
            float zg = 1.f / (1.f + expf(-(giz + ghz)));
            float ng = tanhf(fmaf(rg, ghn, gin));
            float hold = hown[o][r];
            float hn = fmaf(zg, hold, (1.f - zg)*ng);
            hns[r][o] = hn;
            hown[o][r] = hn;
            if (lead && t + 1 < TT) __stcg(&hpub[(row0 + r)*HD + o], hn);
        }
        __syncthreads();
        if (lead && tid == 0 && t + 1 < TT) {
            __threadfence();
            bar_arrive(&g_hflag[t + 1]);
        }

        if (tid < RPB) {
            float s = 0.f;
            #pragma unroll 8
            for (int h = 0; h < HD; h++) s = fmaf(hns[tid][h], wsc[h], s);
            s_score[tid] += s;
        }
        __syncthreads();   // protect xs/meta/hns for next iteration
    }

    // ---- epilogue: own rows only (h local in hown)
    for (int task = tid; task < RPB*80; task += NTHR) {
        int r  = task / 80, od = task % 80;
        int row = row0 + r;
        int k = row / NN, n = row % NN;
        int c = od / TT, tt = od % TT;
        const float* wr = dyw + od*HD;
        float acc = dyb[od];
        #pragma unroll 8
        for (int h = 0; h < HD; h++) acc = fmaf(hown[h][r], wr[h], acc);
        out[((k*TT + tt)*NN + n)*2 + c] = fmaxf(acc, 0.f);
    }
    if (tid < RPB)
        out[KK*TT*NN*2 + row0 + tid] = s_score[tid] + (float)TT * bsc[0];
}

// ---------------------------------------------------------------------------
extern "C" void kernel_launch(void* const* d_in, const int* in_sizes, int n_in,
                              void* d_out, int out_size) {
    const float* hx    = (const float*)d_in[0];
    const float* cur   = (const float*)d_in[1];
    const float* ypath = (const float*)d_in[2];
    const float* img   = (const float*)d_in[3];
    const float* c1w   = (const float*)d_in[4];
    const float* c1b   = (const float*)d_in[5];
    const float* c2w   = (const float*)d_in[6];
    const float* c2b   = (const float*)d_in[7];
    const float* fvw   = (const float*)d_in[8];
    const float* fvb   = (const float*)d_in[9];
    const float* wih   = (const float*)d_in[10];
    const float* whh   = (const float*)d_in[11];
    const float* bih   = (const float*)d_in[12];
    const float* bhh   = (const float*)d_in[13];
    const float* scfw  = (const float*)d_in[14];
    const float* scfb  = (const float*)d_in[15];
    const float* wsc   = (const float*)d_in[16];
    const float* bsc   = (const float*)d_in[17];
    const float* dyw   = (const float*)d_in[18];
    const float* dyb   = (const float*)d_in[19];
    float* out = (float*)d_out;

    k_conv1<<<(16*80*80 + 255)/256, 256>>>(img, c1w, c1b);
    k_conv2<<<dim3(5, 5, 32), 256>>>(c2w, c2b);
    k_pre<<<PREP_B + XPRE_B + BINS_B, 256>>>(hx, wih, whh, scfw,
                                             ypath, cur, fvw, fvb);
    k_steps<<<NBLK, NTHR>>>(scfb, bih, bhh, wsc, dyw, dyb, bsc, out);
}